// round 5
// baseline (speedup 1.0000x reference)
#include <cuda_runtime.h>
#include <math.h>
#include <stdint.h>

#define B_ 2
#define T_ 2048
#define C_ 1024
#define H_ 16
#define D_ 64
#define M_ 4096
#define K2L 0.18033688f   // 0.125 * log2(e)

// Scratch (allocation-free)
__device__ float g_xr[M_*C_];
__device__ float g_Wr[4][C_*C_];
__device__ float g_Q [M_*C_];
__device__ float g_K [M_*C_];
__device__ float g_Vt[B_*H_*D_*T_];
__device__ float g_AO[M_*C_];

// ---------------------------------------------------------------------------
__device__ __forceinline__ float tf32r(float x) {
    uint32_t u; asm("cvt.rna.tf32.f32 %0, %1;" : "=r"(u) : "f"(x));
    return __uint_as_float(u);
}
__host__ __device__ __forceinline__ int perm8(int k) { return ((k & 3) << 1) | (k >> 2); }
__device__ __forceinline__ uint32_t s2u(const void* p) {
    return (uint32_t)__cvta_generic_to_shared(p);
}
__device__ __forceinline__ void cpa16(uint32_t d, const void* s) {
    asm volatile("cp.async.cg.shared.global [%0], [%1], 16;\n" :: "r"(d), "l"(s));
}
#define CPCOMMIT() asm volatile("cp.async.commit_group;\n")
#define CPWAIT0()  asm volatile("cp.async.wait_group 0;\n")
__device__ __forceinline__ float ex2f(float x) {
    float y; asm("ex2.approx.ftz.f32 %0, %1;" : "=f"(y) : "f"(x)); return y;
}
__device__ __forceinline__ void mma_tf32(float* c, const uint32_t* a, const uint32_t* b) {
    asm volatile(
        "mma.sync.aligned.m16n8k8.row.col.f32.tf32.tf32.f32 "
        "{%0,%1,%2,%3}, {%4,%5,%6,%7}, {%8,%9}, {%0,%1,%2,%3};\n"
        : "+f"(c[0]), "+f"(c[1]), "+f"(c[2]), "+f"(c[3])
        : "r"(a[0]), "r"(a[1]), "r"(a[2]), "r"(a[3]), "r"(b[0]), "r"(b[1]));
}

// ---------------------------------------------------------------------------
// Prepass: round to tf32 bits + permute k within 8-groups
// ---------------------------------------------------------------------------
__global__ void prep(const float* __restrict__ src, float* __restrict__ dst, int n) {
    int i = (blockIdx.x * blockDim.x + threadIdx.x) * 4;
    if (i >= n) return;
    float4 v = *(const float4*)(src + i);
    int base = i & ~7, off = i & 4;
    dst[base + perm8(off + 0)] = tf32r(v.x);
    dst[base + perm8(off + 1)] = tf32r(v.y);
    dst[base + perm8(off + 2)] = tf32r(v.z);
    dst[base + perm8(off + 3)] = tf32r(v.w);
}

// ---------------------------------------------------------------------------
// GEMM-NT (tf32): C[m][n] = sum_k A[m][k]*B[n][k].  M=4096,N=K=1024 fixed.
// A,B pre-rounded + k-permuted. 128x128x32 tile, 256 thr, 2-stage cp.async.
// MODE 0: plain fp32 out.  MODE 1: round+perm cols (Q/K).  MODE 2: V^T out.
// ---------------------------------------------------------------------------
#define GST 36
#define GEMM_SMEM (4 * 128 * GST * 4)   // 2 stages x (A+B) x 128x36 floats

template<int MODE>
__global__ void __launch_bounds__(256)
gemm_tc(const float* __restrict__ A, const float* __restrict__ Bm, float* __restrict__ Cm)
{
    extern __shared__ float sh[];
    float* As = sh;                  // [2][128][GST]
    float* Bs = sh + 2 * 128 * GST;  // [2][128][GST]

    const int tid = threadIdx.x, lane = tid & 31, warp = tid >> 5;
    const int gid = lane >> 2, tig = lane & 3;
    const int wm = warp & 3, wn = warp >> 2;
    const int bm = blockIdx.y * 128, bn = blockIdx.x * 128;
    const int frow = tid >> 3, fcol = (tid & 7) << 2;
    const int ko2 = 2 * tig;

    float acc[2][8][4];
    #pragma unroll
    for (int mt = 0; mt < 2; mt++)
        #pragma unroll
        for (int nt = 0; nt < 8; nt++)
            #pragma unroll
            for (int e = 0; e < 4; e++) acc[mt][nt][e] = 0.f;

    auto loadst = [&](int s, int kt) {
        #pragma unroll
        for (int p = 0; p < 4; p++) {
            int row = frow + p * 32;
            cpa16(s2u(&As[(s * 128 + row) * GST + fcol]),
                  &A[(long)(bm + row) * C_ + kt + fcol]);
            cpa16(s2u(&Bs[(s * 128 + row) * GST + fcol]),
                  &Bm[(long)(bn + row) * C_ + kt + fcol]);
        }
    };

    loadst(0, 0); CPCOMMIT();

    #pragma unroll 2
    for (int t = 0; t < 32; t++) {
        CPWAIT0(); __syncthreads();
        if (t + 1 < 32) { loadst((t + 1) & 1, (t + 1) * 32); CPCOMMIT(); }
        const float* as = As + (t & 1) * 128 * GST;
        const float* bs = Bs + (t & 1) * 128 * GST;
        #pragma unroll
        for (int ks = 0; ks < 4; ks++) {
            int ko = ks * 8 + ko2;
            uint32_t a[2][4];
            #pragma unroll
            for (int mt = 0; mt < 2; mt++) {
                int r = wm * 32 + mt * 16 + gid;
                uint2 lo = *(const uint2*)&as[r * GST + ko];
                uint2 hi = *(const uint2*)&as[(r + 8) * GST + ko];
                a[mt][0] = lo.x; a[mt][1] = hi.x; a[mt][2] = lo.y; a[mt][3] = hi.y;
            }
            #pragma unroll
            for (int nt = 0; nt < 8; nt++) {
                int r = wn * 64 + nt * 8 + gid;
                uint2 bv = *(const uint2*)&bs[r * GST + ko];
                uint32_t b[2] = { bv.x, bv.y };
                mma_tf32(acc[0][nt], a[0], b);
                mma_tf32(acc[1][nt], a[1], b);
            }
        }
    }

    #pragma unroll
    for (int mt = 0; mt < 2; mt++) {
        #pragma unroll
        for (int nt = 0; nt < 8; nt++) {
            int r1 = bm + wm * 32 + mt * 16 + gid;
            int r2 = r1 + 8;
            int n0 = bn + wn * 64 + nt * 8 + 2 * tig;
            if (MODE == 0) {
                *(float2*)&Cm[(long)r1 * C_ + n0] = make_float2(acc[mt][nt][0], acc[mt][nt][1]);
                *(float2*)&Cm[(long)r2 * C_ + n0] = make_float2(acc[mt][nt][2], acc[mt][nt][3]);
            } else if (MODE == 1) {
                int na = (n0 & ~7) | perm8(n0 & 7);
                int nb = ((n0 + 1) & ~7) | perm8((n0 + 1) & 7);
                Cm[(long)r1 * C_ + na] = tf32r(acc[mt][nt][0]);
                Cm[(long)r1 * C_ + nb] = tf32r(acc[mt][nt][1]);
                Cm[(long)r2 * C_ + na] = tf32r(acc[mt][nt][2]);
                Cm[(long)r2 * C_ + nb] = tf32r(acc[mt][nt][3]);
            } else {
                #pragma unroll
                for (int e = 0; e < 4; e++) {
                    int m = (e < 2) ? r1 : r2;
                    int n = n0 + (e & 1);
                    int b = m >> 11, tt = m & 2047;
                    int tp = (tt & ~7) | perm8(tt & 7);
                    int h = n >> 6, d = n & 63;
                    Cm[(long)(((b << 4) + h) * 64 + d) * T_ + tp] = tf32r(acc[mt][nt][e]);
                }
            }
        }
    }
}

// ---------------------------------------------------------------------------
// Flash attention (causal), tf32 mma. Grid (32, 32), 128 thr = 4 warps.
// Inputs pre-rounded + permuted; V pre-transposed. All frag loads LDS.64.
// ---------------------------------------------------------------------------
#define AST 68
#define ATTN_SMEM (3 * 64 * AST * 4)

__global__ void __launch_bounds__(128)
attn_tc()
{
    extern __shared__ float sh[];
    float* Qs = sh;             // [64][AST]
    float* Ks = sh + 64 * AST;  // [64][AST] -> reused as P
    float* Vs = sh + 2 * 64 * AST;  // V^T tile [d][c-perm]

    const int qb = gridDim.x - 1 - blockIdx.x;   // big tiles first
    const int bh = blockIdx.y, bb = bh >> 4, h = bh & 15;
    const int tid = threadIdx.x, lane = tid & 31, warp = tid >> 5;
    const int gid = lane >> 2, tig = lane & 3;
    const int m0 = warp * 16;
    const int ko2 = 2 * tig;
    const int pe = perm8(2 * tig), po = perm8(2 * tig + 1);

    // Q fill (verbatim rows: already rounded + permuted)
    #pragma unroll
    for (int j = 0; j < 8; j++) {
        int c = tid + j * 128;
        int row = c >> 4, ch = (c & 15) << 2;
        cpa16(s2u(&Qs[row * AST + ch]),
              &g_Q[((long)(bb * T_ + qb * 64 + row)) * C_ + h * 64 + ch]);
    }
    CPCOMMIT(); CPWAIT0(); __syncthreads();

    float mr0 = -INFINITY, mr1 = -INFINITY, l0 = 0.f, l1 = 0.f;
    float oacc[8][4];
    #pragma unroll
    for (int nt = 0; nt < 8; nt++)
        #pragma unroll
        for (int e = 0; e < 4; e++) oacc[nt][e] = 0.f;

    for (int kb = 0; kb <= qb; kb++) {
        __syncthreads();
        const long kbase = ((long)(bb * T_ + kb * 64)) * C_ + h * 64;
        const long vbase = ((long)((bb * 16 + h) * 64)) * T_ + kb * 64;
        #pragma unroll
        for (int j = 0; j < 8; j++) {
            int c = tid + j * 128;
            int row = c >> 4, ch = (c & 15) << 2;
            cpa16(s2u(&Ks[row * AST + ch]), &g_K [kbase + (long)row * C_ + ch]);
            cpa16(s2u(&Vs[row * AST + ch]), &g_Vt[vbase + (long)row * T_ + ch]);
        }
        CPCOMMIT(); CPWAIT0(); __syncthreads();

        // ---- S = Q @ K^T ----
        float sacc[8][4];
        #pragma unroll
        for (int nt = 0; nt < 8; nt++)
            #pragma unroll
            for (int e = 0; e < 4; e++) sacc[nt][e] = 0.f;

        #pragma unroll
        for (int ks = 0; ks < 8; ks++) {
            int ko = ks * 8 + ko2;
            uint2 lo = *(const uint2*)&Qs[(m0 + gid) * AST + ko];
            uint2 hi = *(const uint2*)&Qs[(m0 + 8 + gid) * AST + ko];
            uint32_t a[4] = { lo.x, hi.x, lo.y, hi.y };
            #pragma unroll
            for (int nt = 0; nt < 8; nt++) {
                uint2 bv = *(const uint2*)&Ks[(nt * 8 + gid) * AST + ko];
                uint32_t b[2] = { bv.x, bv.y };
                mma_tf32(sacc[nt], a, b);
            }
        }

        // ---- softmax (log2 domain) ----
        float mx0 = -INFINITY, mx1 = -INFINITY;
        #pragma unroll
        for (int nt = 0; nt < 8; nt++) {
            #pragma unroll
            for (int e = 0; e < 4; e++) {
                float s = sacc[nt][e] * K2L;
                if (kb == qb) {
                    int rg = m0 + gid + ((e >> 1) << 3);
                    int cg = nt * 8 + 2 * tig + (e & 1);
                    if (cg > rg) s = -INFINITY;
                }
                sacc[nt][e] = s;
            }
            mx0 = fmaxf(mx0, fmaxf(sacc[nt][0], sacc[nt][1]));
            mx1 = fmaxf(mx1, fmaxf(sacc[nt][2], sacc[nt][3]));
        }
        mx0 = fmaxf(mx0, __shfl_xor_sync(~0u, mx0, 1));
        mx0 = fmaxf(mx0, __shfl_xor_sync(~0u, mx0, 2));
        mx1 = fmaxf(mx1, __shfl_xor_sync(~0u, mx1, 1));
        mx1 = fmaxf(mx1, __shfl_xor_sync(~0u, mx1, 2));
        float mn0 = fmaxf(mr0, mx0), mn1 = fmaxf(mr1, mx1);
        float al0 = ex2f(mr0 - mn0), al1 = ex2f(mr1 - mn1);
        float rs0 = 0.f, rs1 = 0.f;
        #pragma unroll
        for (int nt = 0; nt < 8; nt++) {
            sacc[nt][0] = ex2f(sacc[nt][0] - mn0); rs0 += sacc[nt][0];
            sacc[nt][1] = ex2f(sacc[nt][1] - mn0); rs0 += sacc[nt][1];
            sacc[nt][2] = ex2f(sacc[nt][2] - mn1); rs1 += sacc[nt][2];
            sacc[nt][3] = ex2f(sacc[nt][3] - mn1); rs1 += sacc[nt][3];
        }
        rs0 += __shfl_xor_sync(~0u, rs0, 1);
        rs0 += __shfl_xor_sync(~0u, rs0, 2);
        rs1 += __shfl_xor_sync(~0u, rs1, 1);
        rs1 += __shfl_xor_sync(~0u, rs1, 2);
        l0 = l0 * al0 + rs0;  l1 = l1 * al1 + rs1;
        mr0 = mn0;  mr1 = mn1;
        #pragma unroll
        for (int nt = 0; nt < 8; nt++) {
            oacc[nt][0] *= al0; oacc[nt][1] *= al0;
            oacc[nt][2] *= al1; oacc[nt][3] *= al1;
        }

        // ---- P -> Ks buffer (permuted, tf32-rounded) ----
        __syncthreads();
        #pragma unroll
        for (int nt = 0; nt < 8; nt++) {
            Ks[(m0 + gid) * AST + nt * 8 + pe]     = tf32r(sacc[nt][0]);
            Ks[(m0 + gid) * AST + nt * 8 + po]     = tf32r(sacc[nt][1]);
            Ks[(m0 + 8 + gid) * AST + nt * 8 + pe] = tf32r(sacc[nt][2]);
            Ks[(m0 + 8 + gid) * AST + nt * 8 + po] = tf32r(sacc[nt][3]);
        }
        __syncwarp();

        // ---- O += P @ V ----
        #pragma unroll
        for (int ks = 0; ks < 8; ks++) {
            int ko = ks * 8 + ko2;
            uint2 lo = *(const uint2*)&Ks[(m0 + gid) * AST + ko];
            uint2 hi = *(const uint2*)&Ks[(m0 + 8 + gid) * AST + ko];
            uint32_t a[4] = { lo.x, hi.x, lo.y, hi.y };
            #pragma unroll
            for (int nt = 0; nt < 8; nt++) {
                uint2 bv = *(const uint2*)&Vs[(nt * 8 + gid) * AST + ko];
                uint32_t b[2] = { bv.x, bv.y };
                mma_tf32(oacc[nt], a, b);
            }
        }
    }

    // ---- finalize: AO rounded + permuted for O-projection GEMM ----
    float inv0 = 1.f / l0, inv1 = 1.f / l1;
    long base = ((long)(bb * T_ + qb * 64 + m0 + gid)) * C_ + h * 64;
    #pragma unroll
    for (int nt = 0; nt < 8; nt++) {
        g_AO[base + nt * 8 + pe]           = tf32r(oacc[nt][0] * inv0);
        g_AO[base + nt * 8 + po]           = tf32r(oacc[nt][1] * inv0);
        g_AO[base + 8L * C_ + nt * 8 + pe] = tf32r(oacc[nt][2] * inv1);
        g_AO[base + 8L * C_ + nt * 8 + po] = tf32r(oacc[nt][3] * inv1);
    }
}

// ---------------------------------------------------------------------------
extern "C" void kernel_launch(void* const* d_in, const int* in_sizes, int n_in,
                              void* d_out, int out_size)
{
    const float* x  = (const float*)d_in[0];
    const float* Wq = (const float*)d_in[1];
    const float* Wk = (const float*)d_in[2];
    const float* Wv = (const float*)d_in[3];
    const float* Wo = (const float*)d_in[4];
    float* out = (float*)d_out;

    float *xr, *Wr, *Q, *K, *Vt, *AO;
    cudaGetSymbolAddress((void**)&xr, g_xr);
    cudaGetSymbolAddress((void**)&Wr, g_Wr);
    cudaGetSymbolAddress((void**)&Q,  g_Q);
    cudaGetSymbolAddress((void**)&K,  g_K);
    cudaGetSymbolAddress((void**)&Vt, g_Vt);
    cudaGetSymbolAddress((void**)&AO, g_AO);

    // Unconditional (no static guards — harness rule). Not a stream op;
    // capture-safe and idempotent.
    cudaFuncSetAttribute(gemm_tc<0>, cudaFuncAttributeMaxDynamicSharedMemorySize, GEMM_SMEM);
    cudaFuncSetAttribute(gemm_tc<1>, cudaFuncAttributeMaxDynamicSharedMemorySize, GEMM_SMEM);
    cudaFuncSetAttribute(gemm_tc<2>, cudaFuncAttributeMaxDynamicSharedMemorySize, GEMM_SMEM);
    cudaFuncSetAttribute(attn_tc,    cudaFuncAttributeMaxDynamicSharedMemorySize, ATTN_SMEM);

    prep<<<4096, 256>>>(x,  xr, M_ * C_);
    prep<<<1024, 256>>>(Wq, Wr + 0L * C_ * C_, C_ * C_);
    prep<<<1024, 256>>>(Wk, Wr + 1L * C_ * C_, C_ * C_);
    prep<<<1024, 256>>>(Wv, Wr + 2L * C_ * C_, C_ * C_);
    prep<<<1024, 256>>>(Wo, Wr + 3L * C_ * C_, C_ * C_);

    dim3 gg(C_ / 128, M_ / 128);   // (8, 32)
    gemm_tc<1><<<gg, 256, GEMM_SMEM>>>(xr, Wr + 0L * C_ * C_, Q);
    gemm_tc<1><<<gg, 256, GEMM_SMEM>>>(xr, Wr + 1L * C_ * C_, K);
    gemm_tc<2><<<gg, 256, GEMM_SMEM>>>(xr, Wr + 2L * C_ * C_, Vt);

    attn_tc<<<dim3(T_ / 64, B_ * H_), 128, ATTN_SMEM>>>();

    gemm_tc<0><<<gg, 256, GEMM_SMEM>>>(AO, Wr + 3L * C_ * C_, out);
}

// round 8
// speedup vs baseline: 1.0072x; 1.0072x over previous
#include <cuda_runtime.h>
#include <math.h>
#include <stdint.h>

#define B_ 2
#define T_ 2048
#define C_ 1024
#define H_ 16
#define D_ 64
#define M_ 4096
#define K2L 0.18033688f   // 0.125 * log2(e)

// Scratch (allocation-free)
__device__ float g_xr[M_*C_];
__device__ float g_Wr[4][C_*C_];
__device__ float g_Q [M_*C_];
__device__ float g_K [M_*C_];
__device__ float g_V [M_*C_];
__device__ float g_Vt[B_*H_*D_*T_];
__device__ float g_AO[M_*C_];

// ---------------------------------------------------------------------------
__device__ __forceinline__ float tf32r(float x) {
    uint32_t u; asm("cvt.rna.tf32.f32 %0, %1;" : "=r"(u) : "f"(x));
    return __uint_as_float(u);
}
__host__ __device__ __forceinline__ int perm8(int k) { return ((k & 3) << 1) | (k >> 2); }
__device__ __forceinline__ uint32_t s2u(const void* p) {
    return (uint32_t)__cvta_generic_to_shared(p);
}
__device__ __forceinline__ void cpa16(uint32_t d, const void* s) {
    asm volatile("cp.async.cg.shared.global [%0], [%1], 16;\n" :: "r"(d), "l"(s));
}
#define CPCOMMIT() asm volatile("cp.async.commit_group;\n")
#define CPWAIT0()  asm volatile("cp.async.wait_group 0;\n")
__device__ __forceinline__ float ex2f(float x) {
    float y; asm("ex2.approx.ftz.f32 %0, %1;" : "=f"(y) : "f"(x)); return y;
}
__device__ __forceinline__ void mma_tf32(float* c, const uint32_t* a, const uint32_t* b) {
    asm volatile(
        "mma.sync.aligned.m16n8k8.row.col.f32.tf32.tf32.f32 "
        "{%0,%1,%2,%3}, {%4,%5,%6,%7}, {%8,%9}, {%0,%1,%2,%3};\n"
        : "+f"(c[0]), "+f"(c[1]), "+f"(c[2]), "+f"(c[3])
        : "r"(a[0]), "r"(a[1]), "r"(a[2]), "r"(a[3]), "r"(b[0]), "r"(b[1]));
}

// ---------------------------------------------------------------------------
// Prepass: round to tf32 + permute k within 8-groups.
// ---------------------------------------------------------------------------
__global__ void prep_x(const float* __restrict__ src, float* __restrict__ dst) {
    int i = (blockIdx.x * blockDim.x + threadIdx.x) * 4;
    float4 v = *(const float4*)(src + i);
    int base = i & ~7, off = i & 4;
    dst[base + perm8(off + 0)] = tf32r(v.x);
    dst[base + perm8(off + 1)] = tf32r(v.y);
    dst[base + perm8(off + 2)] = tf32r(v.z);
    dst[base + perm8(off + 3)] = tf32r(v.w);
}
__global__ void prep_w(const float* w0, const float* w1, const float* w2,
                       const float* w3, float* __restrict__ dst) {
    const float* src = (blockIdx.y == 0) ? w0 : (blockIdx.y == 1) ? w1
                     : (blockIdx.y == 2) ? w2 : w3;
    float* d = dst + (long)blockIdx.y * C_ * C_;
    int i = (blockIdx.x * blockDim.x + threadIdx.x) * 4;
    float4 v = *(const float4*)(src + i);
    int base = i & ~7, off = i & 4;
    d[base + perm8(off + 0)] = tf32r(v.x);
    d[base + perm8(off + 1)] = tf32r(v.y);
    d[base + perm8(off + 2)] = tf32r(v.z);
    d[base + perm8(off + 3)] = tf32r(v.w);
}

// ---------------------------------------------------------------------------
// GEMM-NT (tf32): C[m][n] = sum_k A[m][k]*B[n][k]. K=1024 fixed.
// 128x128x32 tile, 256 thr, 2-stage cp.async, all frag loads LDS.64.
// MODE 0: plain fp32 out (Cm).
// MODE 3: fused QKV epilogue: n<1024 -> Q (round+perm), <2048 -> K (round+perm),
//         else -> V plain fp32.
// ---------------------------------------------------------------------------
#define GST 36
#define GEMM_SMEM (4 * 128 * GST * 4)

template<int MODE>
__global__ void __launch_bounds__(256)
gemm_tc(const float* __restrict__ A, const float* __restrict__ Bm,
        float* __restrict__ Cm, float* __restrict__ Cq,
        float* __restrict__ Ck, float* __restrict__ Cv)
{
    extern __shared__ float sh[];
    float* As = sh;
    float* Bs = sh + 2 * 128 * GST;

    const int tid = threadIdx.x, lane = tid & 31, warp = tid >> 5;
    const int gid = lane >> 2, tig = lane & 3;
    const int wm = warp & 3, wn = warp >> 2;
    const int bm = blockIdx.y * 128, bn = blockIdx.x * 128;
    const int frow = tid >> 3, fcol = (tid & 7) << 2;
    const int ko2 = 2 * tig;

    float acc[2][8][4];
    #pragma unroll
    for (int mt = 0; mt < 2; mt++)
        #pragma unroll
        for (int nt = 0; nt < 8; nt++)
            #pragma unroll
            for (int e = 0; e < 4; e++) acc[mt][nt][e] = 0.f;

    auto loadst = [&](int s, int kt) {
        #pragma unroll
        for (int p = 0; p < 4; p++) {
            int row = frow + p * 32;
            cpa16(s2u(&As[(s * 128 + row) * GST + fcol]),
                  &A[(long)(bm + row) * C_ + kt + fcol]);
            cpa16(s2u(&Bs[(s * 128 + row) * GST + fcol]),
                  &Bm[(long)(bn + row) * C_ + kt + fcol]);
        }
    };

    loadst(0, 0); CPCOMMIT();

    #pragma unroll 2
    for (int t = 0; t < 32; t++) {
        CPWAIT0(); __syncthreads();
        if (t + 1 < 32) { loadst((t + 1) & 1, (t + 1) * 32); CPCOMMIT(); }
        const float* as = As + (t & 1) * 128 * GST;
        const float* bs = Bs + (t & 1) * 128 * GST;
        #pragma unroll
        for (int ks = 0; ks < 4; ks++) {
            int ko = ks * 8 + ko2;
            uint32_t a[2][4];
            #pragma unroll
            for (int mt = 0; mt < 2; mt++) {
                int r = wm * 32 + mt * 16 + gid;
                uint2 lo = *(const uint2*)&as[r * GST + ko];
                uint2 hi = *(const uint2*)&as[(r + 8) * GST + ko];
                a[mt][0] = lo.x; a[mt][1] = hi.x; a[mt][2] = lo.y; a[mt][3] = hi.y;
            }
            #pragma unroll
            for (int nt = 0; nt < 8; nt++) {
                int r = wn * 64 + nt * 8 + gid;
                uint2 bv = *(const uint2*)&bs[r * GST + ko];
                uint32_t b[2] = { bv.x, bv.y };
                mma_tf32(acc[0][nt], a[0], b);
                mma_tf32(acc[1][nt], a[1], b);
            }
        }
    }

    #pragma unroll
    for (int mt = 0; mt < 2; mt++) {
        #pragma unroll
        for (int nt = 0; nt < 8; nt++) {
            int r1 = bm + wm * 32 + mt * 16 + gid;
            int r2 = r1 + 8;
            int n0 = bn + wn * 64 + nt * 8 + 2 * tig;
            if (MODE == 0) {
                *(float2*)&Cm[(long)r1 * C_ + n0] = make_float2(acc[mt][nt][0], acc[mt][nt][1]);
                *(float2*)&Cm[(long)r2 * C_ + n0] = make_float2(acc[mt][nt][2], acc[mt][nt][3]);
            } else {
                int w  = n0 >> 10;          // 0=Q, 1=K, 2=V
                int nc = n0 & 1023;
                if (w == 2) {
                    *(float2*)&Cv[(long)r1 * C_ + nc] = make_float2(acc[mt][nt][0], acc[mt][nt][1]);
                    *(float2*)&Cv[(long)r2 * C_ + nc] = make_float2(acc[mt][nt][2], acc[mt][nt][3]);
                } else {
                    float* dst = (w == 0) ? Cq : Ck;
                    int na = (nc & ~7) | perm8(nc & 7);
                    int nb = ((nc + 1) & ~7) | perm8((nc + 1) & 7);
                    dst[(long)r1 * C_ + na] = tf32r(acc[mt][nt][0]);
                    dst[(long)r1 * C_ + nb] = tf32r(acc[mt][nt][1]);
                    dst[(long)r2 * C_ + na] = tf32r(acc[mt][nt][2]);
                    dst[(long)r2 * C_ + nb] = tf32r(acc[mt][nt][3]);
                }
            }
        }
    }
}

// ---------------------------------------------------------------------------
// V transpose: g_Vt[((b*16+h)*64+d)][t0+perm(tx)] = tf32r(V[t0+tx][h*64+d])
// 32x32 smem tiles; coalesced reads and writes.
// Grid (T_/32, C_/32, B_), block (32, 8).
// ---------------------------------------------------------------------------
__global__ void vtrans()
{
    __shared__ float tile[32][33];
    const int t0 = blockIdx.x * 32, c0 = blockIdx.y * 32, b = blockIdx.z;
    const int tx = threadIdx.x, ty = threadIdx.y;

    #pragma unroll
    for (int r = 0; r < 4; r++) {
        int t = ty + r * 8;
        tile[t][tx] = g_V[(long)(b * T_ + t0 + t) * C_ + c0 + tx];
    }
    __syncthreads();

    const int txp = (tx & ~7) | perm8(tx & 7);
    #pragma unroll
    for (int r = 0; r < 4; r++) {
        int cc = c0 + ty + r * 8;          // channel index in [0,1024)
        int h = cc >> 6, d = cc & 63;
        // TRANSPOSED read: value for token t0+tx, channel cc.
        g_Vt[(long)(((b << 4) + h) * 64 + d) * T_ + t0 + txp] =
            tf32r(tile[tx][ty + r * 8]);
    }
}

// ---------------------------------------------------------------------------
// Flash attention (causal), tf32 mma. Grid (32, 32), 128 thr = 4 warps.
// Inputs pre-rounded + permuted; V pre-transposed. All frag loads LDS.64.
// ---------------------------------------------------------------------------
#define AST 68
#define ATTN_SMEM (3 * 64 * AST * 4)

__global__ void __launch_bounds__(128)
attn_tc()
{
    extern __shared__ float sh[];
    float* Qs = sh;                  // [64][AST]
    float* Ks = sh + 64 * AST;       // [64][AST] -> reused as P
    float* Vs = sh + 2 * 64 * AST;   // V^T tile [d][c-perm]

    const int qb = gridDim.x - 1 - blockIdx.x;   // big tiles first
    const int bh = blockIdx.y, bb = bh >> 4, h = bh & 15;
    const int tid = threadIdx.x, lane = tid & 31, warp = tid >> 5;
    const int gid = lane >> 2, tig = lane & 3;
    const int m0 = warp * 16;
    const int ko2 = 2 * tig;
    const int pe = perm8(2 * tig), po = perm8(2 * tig + 1);

    #pragma unroll
    for (int j = 0; j < 8; j++) {
        int c = tid + j * 128;
        int row = c >> 4, ch = (c & 15) << 2;
        cpa16(s2u(&Qs[row * AST + ch]),
              &g_Q[((long)(bb * T_ + qb * 64 + row)) * C_ + h * 64 + ch]);
    }
    CPCOMMIT(); CPWAIT0(); __syncthreads();

    float mr0 = -INFINITY, mr1 = -INFINITY, l0 = 0.f, l1 = 0.f;
    float oacc[8][4];
    #pragma unroll
    for (int nt = 0; nt < 8; nt++)
        #pragma unroll
        for (int e = 0; e < 4; e++) oacc[nt][e] = 0.f;

    for (int kb = 0; kb <= qb; kb++) {
        __syncthreads();
        const long kbase = ((long)(bb * T_ + kb * 64)) * C_ + h * 64;
        const long vbase = ((long)((bb * 16 + h) * 64)) * T_ + kb * 64;
        #pragma unroll
        for (int j = 0; j < 8; j++) {
            int c = tid + j * 128;
            int row = c >> 4, ch = (c & 15) << 2;
            cpa16(s2u(&Ks[row * AST + ch]), &g_K [kbase + (long)row * C_ + ch]);
            cpa16(s2u(&Vs[row * AST + ch]), &g_Vt[vbase + (long)row * T_ + ch]);
        }
        CPCOMMIT(); CPWAIT0(); __syncthreads();

        // ---- S = Q @ K^T ----
        float sacc[8][4];
        #pragma unroll
        for (int nt = 0; nt < 8; nt++)
            #pragma unroll
            for (int e = 0; e < 4; e++) sacc[nt][e] = 0.f;

        #pragma unroll
        for (int ks = 0; ks < 8; ks++) {
            int ko = ks * 8 + ko2;
            uint2 lo = *(const uint2*)&Qs[(m0 + gid) * AST + ko];
            uint2 hi = *(const uint2*)&Qs[(m0 + 8 + gid) * AST + ko];
            uint32_t a[4] = { lo.x, hi.x, lo.y, hi.y };
            #pragma unroll
            for (int nt = 0; nt < 8; nt++) {
                uint2 bv = *(const uint2*)&Ks[(nt * 8 + gid) * AST + ko];
                uint32_t b[2] = { bv.x, bv.y };
                mma_tf32(sacc[nt], a, b);
            }
        }

        // ---- softmax (log2 domain) ----
        float mx0 = -INFINITY, mx1 = -INFINITY;
        #pragma unroll
        for (int nt = 0; nt < 8; nt++) {
            #pragma unroll
            for (int e = 0; e < 4; e++) {
                float s = sacc[nt][e] * K2L;
                if (kb == qb) {
                    int rg = m0 + gid + ((e >> 1) << 3);
                    int cg = nt * 8 + 2 * tig + (e & 1);
                    if (cg > rg) s = -INFINITY;
                }
                sacc[nt][e] = s;
            }
            mx0 = fmaxf(mx0, fmaxf(sacc[nt][0], sacc[nt][1]));
            mx1 = fmaxf(mx1, fmaxf(sacc[nt][2], sacc[nt][3]));
        }
        mx0 = fmaxf(mx0, __shfl_xor_sync(~0u, mx0, 1));
        mx0 = fmaxf(mx0, __shfl_xor_sync(~0u, mx0, 2));
        mx1 = fmaxf(mx1, __shfl_xor_sync(~0u, mx1, 1));
        mx1 = fmaxf(mx1, __shfl_xor_sync(~0u, mx1, 2));
        float mn0 = fmaxf(mr0, mx0), mn1 = fmaxf(mr1, mx1);
        float al0 = ex2f(mr0 - mn0), al1 = ex2f(mr1 - mn1);
        float rs0 = 0.f, rs1 = 0.f;
        #pragma unroll
        for (int nt = 0; nt < 8; nt++) {
            sacc[nt][0] = ex2f(sacc[nt][0] - mn0); rs0 += sacc[nt][0];
            sacc[nt][1] = ex2f(sacc[nt][1] - mn0); rs0 += sacc[nt][1];
            sacc[nt][2] = ex2f(sacc[nt][2] - mn1); rs1 += sacc[nt][2];
            sacc[nt][3] = ex2f(sacc[nt][3] - mn1); rs1 += sacc[nt][3];
        }
        rs0 += __shfl_xor_sync(~0u, rs0, 1);
        rs0 += __shfl_xor_sync(~0u, rs0, 2);
        rs1 += __shfl_xor_sync(~0u, rs1, 1);
        rs1 += __shfl_xor_sync(~0u, rs1, 2);
        l0 = l0 * al0 + rs0;  l1 = l1 * al1 + rs1;
        mr0 = mn0;  mr1 = mn1;
        #pragma unroll
        for (int nt = 0; nt < 8; nt++) {
            oacc[nt][0] *= al0; oacc[nt][1] *= al0;
            oacc[nt][2] *= al1; oacc[nt][3] *= al1;
        }

        // ---- P -> Ks buffer (permuted, tf32-rounded) ----
        __syncthreads();
        #pragma unroll
        for (int nt = 0; nt < 8; nt++) {
            Ks[(m0 + gid) * AST + nt * 8 + pe]     = tf32r(sacc[nt][0]);
            Ks[(m0 + gid) * AST + nt * 8 + po]     = tf32r(sacc[nt][1]);
            Ks[(m0 + 8 + gid) * AST + nt * 8 + pe] = tf32r(sacc[nt][2]);
            Ks[(m0 + 8 + gid) * AST + nt * 8 + po] = tf32r(sacc[nt][3]);
        }
        __syncwarp();

        // ---- O += P @ V ----
        #pragma unroll
        for (int ks = 0; ks < 8; ks++) {
            int ko = ks * 8 + ko2;
            uint2 lo = *(const uint2*)&Ks[(m0 + gid) * AST + ko];
            uint2 hi = *(const uint2*)&Ks[(m0 + 8 + gid) * AST + ko];
            uint32_t a[4] = { lo.x, hi.x, lo.y, hi.y };
            #pragma unroll
            for (int nt = 0; nt < 8; nt++) {
                uint2 bv = *(const uint2*)&Vs[(nt * 8 + gid) * AST + ko];
                uint32_t b[2] = { bv.x, bv.y };
                mma_tf32(oacc[nt], a, b);
            }
        }
    }

    // ---- finalize: AO rounded + permuted for O-projection GEMM ----
    float inv0 = 1.f / l0, inv1 = 1.f / l1;
    long base = ((long)(bb * T_ + qb * 64 + m0 + gid)) * C_ + h * 64;
    #pragma unroll
    for (int nt = 0; nt < 8; nt++) {
        g_AO[base + nt * 8 + pe]           = tf32r(oacc[nt][0] * inv0);
        g_AO[base + nt * 8 + po]           = tf32r(oacc[nt][1] * inv0);
        g_AO[base + 8L * C_ + nt * 8 + pe] = tf32r(oacc[nt][2] * inv1);
        g_AO[base + 8L * C_ + nt * 8 + po] = tf32r(oacc[nt][3] * inv1);
    }
}

// ---------------------------------------------------------------------------
extern "C" void kernel_launch(void* const* d_in, const int* in_sizes, int n_in,
                              void* d_out, int out_size)
{
    const float* x  = (const float*)d_in[0];
    const float* Wq = (const float*)d_in[1];
    const float* Wk = (const float*)d_in[2];
    const float* Wv = (const float*)d_in[3];
    const float* Wo = (const float*)d_in[4];
    float* out = (float*)d_out;

    float *xr, *Wr, *Q, *K, *V, *Vt, *AO;
    cudaGetSymbolAddress((void**)&xr, g_xr);
    cudaGetSymbolAddress((void**)&Wr, g_Wr);
    cudaGetSymbolAddress((void**)&Q,  g_Q);
    cudaGetSymbolAddress((void**)&K,  g_K);
    cudaGetSymbolAddress((void**)&V,  g_V);
    cudaGetSymbolAddress((void**)&Vt, g_Vt);
    cudaGetSymbolAddress((void**)&AO, g_AO);

    cudaFuncSetAttribute(gemm_tc<0>, cudaFuncAttributeMaxDynamicSharedMemorySize, GEMM_SMEM);
    cudaFuncSetAttribute(gemm_tc<3>, cudaFuncAttributeMaxDynamicSharedMemorySize, GEMM_SMEM);
    cudaFuncSetAttribute(attn_tc,    cudaFuncAttributeMaxDynamicSharedMemorySize, ATTN_SMEM);

    prep_x<<<4096, 256>>>(x, xr);
    prep_w<<<dim3(1024, 4), 256>>>(Wq, Wk, Wv, Wo, Wr);

    // Fused QKV projection: B = [Wq; Wk; Wv] rows 0..3071 of g_Wr.
    gemm_tc<3><<<dim3(24, 32), 256, GEMM_SMEM>>>(xr, Wr, nullptr, Q, K, V);

    vtrans<<<dim3(T_ / 32, C_ / 32, B_), dim3(32, 8)>>>();

    attn_tc<<<dim3(T_ / 64, B_ * H_), 128, ATTN_SMEM>>>();

    gemm_tc<0><<<dim3(8, 32), 256, GEMM_SMEM>>>(AO, Wr + 3L * C_ * C_, out,
                                                nullptr, nullptr, nullptr);
}

// round 9
// speedup vs baseline: 1.0156x; 1.0083x over previous
#include <cuda_runtime.h>
#include <math.h>
#include <stdint.h>

#define B_ 2
#define T_ 2048
#define C_ 1024
#define H_ 16
#define D_ 64
#define M_ 4096
#define K2L 0.18033688f   // 0.125 * log2(e)

// Scratch (allocation-free)
__device__ float g_xr[M_*C_];
__device__ float g_Wr[4][C_*C_];
__device__ float g_Q [M_*C_];
__device__ float g_K [M_*C_];
__device__ float g_V [M_*C_];
__device__ float g_Vt[B_*H_*D_*T_];
__device__ float g_AO[M_*C_];

// ---------------------------------------------------------------------------
__device__ __forceinline__ float tf32r(float x) {
    uint32_t u; asm("cvt.rna.tf32.f32 %0, %1;" : "=r"(u) : "f"(x));
    return __uint_as_float(u);
}
__host__ __device__ __forceinline__ int perm8(int k) { return ((k & 3) << 1) | (k >> 2); }
__device__ __forceinline__ uint32_t s2u(const void* p) {
    return (uint32_t)__cvta_generic_to_shared(p);
}
__device__ __forceinline__ void cpa16(uint32_t d, const void* s) {
    asm volatile("cp.async.cg.shared.global [%0], [%1], 16;\n" :: "r"(d), "l"(s));
}
#define CPCOMMIT() asm volatile("cp.async.commit_group;\n")
#define CPWAIT0()  asm volatile("cp.async.wait_group 0;\n")
__device__ __forceinline__ float ex2f(float x) {
    float y; asm("ex2.approx.ftz.f32 %0, %1;" : "=f"(y) : "f"(x)); return y;
}
__device__ __forceinline__ void mma_tf32(float* c, const uint32_t* a, const uint32_t* b) {
    asm volatile(
        "mma.sync.aligned.m16n8k8.row.col.f32.tf32.tf32.f32 "
        "{%0,%1,%2,%3}, {%4,%5,%6,%7}, {%8,%9}, {%0,%1,%2,%3};\n"
        : "+f"(c[0]), "+f"(c[1]), "+f"(c[2]), "+f"(c[3])
        : "r"(a[0]), "r"(a[1]), "r"(a[2]), "r"(a[3]), "r"(b[0]), "r"(b[1]));
}

// ---------------------------------------------------------------------------
// Prepass: round to tf32 + permute k within 8-groups.
// Outputs 0..7 of each group = inputs [0,4,1,5,2,6,3,7] -> two float4 stores.
// ---------------------------------------------------------------------------
__device__ __forceinline__ void prep8(const float* __restrict__ s, float* __restrict__ d) {
    float4 a = *(const float4*)(s);
    float4 b = *(const float4*)(s + 4);
    *(float4*)(d)     = make_float4(tf32r(a.x), tf32r(b.x), tf32r(a.y), tf32r(b.y));
    *(float4*)(d + 4) = make_float4(tf32r(a.z), tf32r(b.z), tf32r(a.w), tf32r(b.w));
}
__global__ void prep_x(const float* __restrict__ src, float* __restrict__ dst) {
    int i = (blockIdx.x * blockDim.x + threadIdx.x) * 8;
    prep8(src + i, dst + i);
}
__global__ void prep_w(const float* w0, const float* w1, const float* w2,
                       const float* w3, float* __restrict__ dst) {
    const float* src = (blockIdx.y == 0) ? w0 : (blockIdx.y == 1) ? w1
                     : (blockIdx.y == 2) ? w2 : w3;
    float* d = dst + (long)blockIdx.y * C_ * C_;
    int i = (blockIdx.x * blockDim.x + threadIdx.x) * 8;
    prep8(src + i, d + i);
}

// ---------------------------------------------------------------------------
// GEMM-NT (tf32): C[m][n] = sum_k A[m][k]*B[n][k]. K=1024 fixed.
// 128x128x32 tile, 256 thr, 2-stage cp.async, all frag loads LDS.64.
// MODE 0: plain fp32 out (Cm).
// MODE 3: fused QKV epilogue: n<1024 -> Q (round+perm), <2048 -> K (round+perm),
//         else -> V plain fp32.
// ---------------------------------------------------------------------------
#define GST 36
#define GEMM_SMEM (4 * 128 * GST * 4)

template<int MODE>
__global__ void __launch_bounds__(256)
gemm_tc(const float* __restrict__ A, const float* __restrict__ Bm,
        float* __restrict__ Cm, float* __restrict__ Cq,
        float* __restrict__ Ck, float* __restrict__ Cv)
{
    extern __shared__ float sh[];
    float* As = sh;
    float* Bs = sh + 2 * 128 * GST;

    const int tid = threadIdx.x, lane = tid & 31, warp = tid >> 5;
    const int gid = lane >> 2, tig = lane & 3;
    const int wm = warp & 3, wn = warp >> 2;
    const int bm = blockIdx.y * 128, bn = blockIdx.x * 128;
    const int frow = tid >> 3, fcol = (tid & 7) << 2;
    const int ko2 = 2 * tig;

    float acc[2][8][4];
    #pragma unroll
    for (int mt = 0; mt < 2; mt++)
        #pragma unroll
        for (int nt = 0; nt < 8; nt++)
            #pragma unroll
            for (int e = 0; e < 4; e++) acc[mt][nt][e] = 0.f;

    auto loadst = [&](int s, int kt) {
        #pragma unroll
        for (int p = 0; p < 4; p++) {
            int row = frow + p * 32;
            cpa16(s2u(&As[(s * 128 + row) * GST + fcol]),
                  &A[(long)(bm + row) * C_ + kt + fcol]);
            cpa16(s2u(&Bs[(s * 128 + row) * GST + fcol]),
                  &Bm[(long)(bn + row) * C_ + kt + fcol]);
        }
    };

    loadst(0, 0); CPCOMMIT();

    #pragma unroll 2
    for (int t = 0; t < 32; t++) {
        CPWAIT0(); __syncthreads();
        if (t + 1 < 32) { loadst((t + 1) & 1, (t + 1) * 32); CPCOMMIT(); }
        const float* as = As + (t & 1) * 128 * GST;
        const float* bs = Bs + (t & 1) * 128 * GST;
        #pragma unroll
        for (int ks = 0; ks < 4; ks++) {
            int ko = ks * 8 + ko2;
            uint32_t a[2][4];
            #pragma unroll
            for (int mt = 0; mt < 2; mt++) {
                int r = wm * 32 + mt * 16 + gid;
                uint2 lo = *(const uint2*)&as[r * GST + ko];
                uint2 hi = *(const uint2*)&as[(r + 8) * GST + ko];
                a[mt][0] = lo.x; a[mt][1] = hi.x; a[mt][2] = lo.y; a[mt][3] = hi.y;
            }
            #pragma unroll
            for (int nt = 0; nt < 8; nt++) {
                int r = wn * 64 + nt * 8 + gid;
                uint2 bv = *(const uint2*)&bs[r * GST + ko];
                uint32_t b[2] = { bv.x, bv.y };
                mma_tf32(acc[0][nt], a[0], b);
                mma_tf32(acc[1][nt], a[1], b);
            }
        }
    }

    #pragma unroll
    for (int mt = 0; mt < 2; mt++) {
        #pragma unroll
        for (int nt = 0; nt < 8; nt++) {
            int r1 = bm + wm * 32 + mt * 16 + gid;
            int r2 = r1 + 8;
            int n0 = bn + wn * 64 + nt * 8 + 2 * tig;
            if (MODE == 0) {
                *(float2*)&Cm[(long)r1 * C_ + n0] = make_float2(acc[mt][nt][0], acc[mt][nt][1]);
                *(float2*)&Cm[(long)r2 * C_ + n0] = make_float2(acc[mt][nt][2], acc[mt][nt][3]);
            } else {
                int w  = n0 >> 10;          // 0=Q, 1=K, 2=V
                int nc = n0 & 1023;
                if (w == 2) {
                    *(float2*)&Cv[(long)r1 * C_ + nc] = make_float2(acc[mt][nt][0], acc[mt][nt][1]);
                    *(float2*)&Cv[(long)r2 * C_ + nc] = make_float2(acc[mt][nt][2], acc[mt][nt][3]);
                } else {
                    float* dst = (w == 0) ? Cq : Ck;
                    int na = (nc & ~7) | perm8(nc & 7);
                    int nb = ((nc + 1) & ~7) | perm8((nc + 1) & 7);
                    dst[(long)r1 * C_ + na] = tf32r(acc[mt][nt][0]);
                    dst[(long)r1 * C_ + nb] = tf32r(acc[mt][nt][1]);
                    dst[(long)r2 * C_ + na] = tf32r(acc[mt][nt][2]);
                    dst[(long)r2 * C_ + nb] = tf32r(acc[mt][nt][3]);
                }
            }
        }
    }
}

// ---------------------------------------------------------------------------
// V transpose: g_Vt[((b*16+h)*64+d)][t0+perm(tx)] = tf32r(V[t0+tx][h*64+d])
// ---------------------------------------------------------------------------
__global__ void vtrans()
{
    __shared__ float tile[32][33];
    const int t0 = blockIdx.x * 32, c0 = blockIdx.y * 32, b = blockIdx.z;
    const int tx = threadIdx.x, ty = threadIdx.y;

    #pragma unroll
    for (int r = 0; r < 4; r++) {
        int t = ty + r * 8;
        tile[t][tx] = g_V[(long)(b * T_ + t0 + t) * C_ + c0 + tx];
    }
    __syncthreads();

    const int txp = (tx & ~7) | perm8(tx & 7);
    #pragma unroll
    for (int r = 0; r < 4; r++) {
        int cc = c0 + ty + r * 8;
        int h = cc >> 6, d = cc & 63;
        g_Vt[(long)(((b << 4) + h) * 64 + d) * T_ + t0 + txp] =
            tf32r(tile[tx][ty + r * 8]);
    }
}

// ---------------------------------------------------------------------------
// Flash attention (causal), tf32 mma. Grid (32, 32), 128 thr = 4 warps.
// DOUBLE-BUFFERED KV: prefetch tile kb+1 (issued post-sync) overlaps compute
// of tile kb. P reuses the CURRENT K stage; prefetch targets the other stage.
// smem: Q[64][68] + K[2][64][68] + V[2][64][68] = 87KB -> 2 blocks/SM.
// ---------------------------------------------------------------------------
#define AST 68
#define ATILE (64 * AST)
#define ATTN_SMEM (5 * ATILE * 4)

__global__ void __launch_bounds__(128)
attn_tc()
{
    extern __shared__ float sh[];
    float* Qs = sh;                        // [64][AST]

    const int qb = gridDim.x - 1 - blockIdx.x;   // big tiles first
    const int bh = blockIdx.y, bb = bh >> 4, h = bh & 15;
    const int tid = threadIdx.x, lane = tid & 31, warp = tid >> 5;
    const int gid = lane >> 2, tig = lane & 3;
    const int m0 = warp * 16;
    const int ko2 = 2 * tig;
    const int pe = perm8(2 * tig), po = perm8(2 * tig + 1);

    const long kbase0 = ((long)(bb * T_)) * C_ + h * 64;
    const long vbase0 = ((long)((bb * 16 + h) * 64)) * T_;

    auto load_kv = [&](int kb, int s) {
        float* Ks = sh + ATILE * (1 + s);
        float* Vs = sh + ATILE * (3 + s);
        const long kbase = kbase0 + (long)(kb * 64) * C_;
        const long vbase = vbase0 + kb * 64;
        #pragma unroll
        for (int j = 0; j < 8; j++) {
            int c = tid + j * 128;
            int row = c >> 4, ch = (c & 15) << 2;
            cpa16(s2u(&Ks[row * AST + ch]), &g_K [kbase + (long)row * C_ + ch]);
            cpa16(s2u(&Vs[row * AST + ch]), &g_Vt[vbase + (long)row * T_ + ch]);
        }
    };

    // Prologue: Q + KV tile 0 in one group.
    #pragma unroll
    for (int j = 0; j < 8; j++) {
        int c = tid + j * 128;
        int row = c >> 4, ch = (c & 15) << 2;
        cpa16(s2u(&Qs[row * AST + ch]),
              &g_Q[kbase0 + (long)(qb * 64 + row) * C_ + ch]);
    }
    load_kv(0, 0);
    CPCOMMIT();

    float mr0 = -INFINITY, mr1 = -INFINITY, l0 = 0.f, l1 = 0.f;
    float oacc[8][4];
    #pragma unroll
    for (int nt = 0; nt < 8; nt++)
        #pragma unroll
        for (int e = 0; e < 4; e++) oacc[nt][e] = 0.f;

    for (int kb = 0; kb <= qb; kb++) {
        const int s = kb & 1;
        float* Ks = sh + ATILE * (1 + s);   // -> reused as P after S-phase
        float* Vs = sh + ATILE * (3 + s);

        CPWAIT0();
        __syncthreads();   // tile kb resident; all warps past tile kb-1
        if (kb < qb) { load_kv(kb + 1, s ^ 1); CPCOMMIT(); }

        // ---- S = Q @ K^T ----
        float sacc[8][4];
        #pragma unroll
        for (int nt = 0; nt < 8; nt++)
            #pragma unroll
            for (int e = 0; e < 4; e++) sacc[nt][e] = 0.f;

        #pragma unroll
        for (int ks = 0; ks < 8; ks++) {
            int ko = ks * 8 + ko2;
            uint2 lo = *(const uint2*)&Qs[(m0 + gid) * AST + ko];
            uint2 hi = *(const uint2*)&Qs[(m0 + 8 + gid) * AST + ko];
            uint32_t a[4] = { lo.x, hi.x, lo.y, hi.y };
            #pragma unroll
            for (int nt = 0; nt < 8; nt++) {
                uint2 bv = *(const uint2*)&Ks[(nt * 8 + gid) * AST + ko];
                uint32_t b[2] = { bv.x, bv.y };
                mma_tf32(sacc[nt], a, b);
            }
        }

        // ---- softmax (log2 domain) ----
        float mx0 = -INFINITY, mx1 = -INFINITY;
        #pragma unroll
        for (int nt = 0; nt < 8; nt++) {
            #pragma unroll
            for (int e = 0; e < 4; e++) {
                float sv = sacc[nt][e] * K2L;
                if (kb == qb) {
                    int rg = m0 + gid + ((e >> 1) << 3);
                    int cg = nt * 8 + 2 * tig + (e & 1);
                    if (cg > rg) sv = -INFINITY;
                }
                sacc[nt][e] = sv;
            }
            mx0 = fmaxf(mx0, fmaxf(sacc[nt][0], sacc[nt][1]));
            mx1 = fmaxf(mx1, fmaxf(sacc[nt][2], sacc[nt][3]));
        }
        mx0 = fmaxf(mx0, __shfl_xor_sync(~0u, mx0, 1));
        mx0 = fmaxf(mx0, __shfl_xor_sync(~0u, mx0, 2));
        mx1 = fmaxf(mx1, __shfl_xor_sync(~0u, mx1, 1));
        mx1 = fmaxf(mx1, __shfl_xor_sync(~0u, mx1, 2));
        float mn0 = fmaxf(mr0, mx0), mn1 = fmaxf(mr1, mx1);
        float al0 = ex2f(mr0 - mn0), al1 = ex2f(mr1 - mn1);
        float rs0 = 0.f, rs1 = 0.f;
        #pragma unroll
        for (int nt = 0; nt < 8; nt++) {
            sacc[nt][0] = ex2f(sacc[nt][0] - mn0); rs0 += sacc[nt][0];
            sacc[nt][1] = ex2f(sacc[nt][1] - mn0); rs0 += sacc[nt][1];
            sacc[nt][2] = ex2f(sacc[nt][2] - mn1); rs1 += sacc[nt][2];
            sacc[nt][3] = ex2f(sacc[nt][3] - mn1); rs1 += sacc[nt][3];
        }
        rs0 += __shfl_xor_sync(~0u, rs0, 1);
        rs0 += __shfl_xor_sync(~0u, rs0, 2);
        rs1 += __shfl_xor_sync(~0u, rs1, 1);
        rs1 += __shfl_xor_sync(~0u, rs1, 2);
        l0 = l0 * al0 + rs0;  l1 = l1 * al1 + rs1;
        mr0 = mn0;  mr1 = mn1;
        #pragma unroll
        for (int nt = 0; nt < 8; nt++) {
            oacc[nt][0] *= al0; oacc[nt][1] *= al0;
            oacc[nt][2] *= al1; oacc[nt][3] *= al1;
        }

        // ---- P -> current K stage (all warps done reading K) ----
        __syncthreads();
        #pragma unroll
        for (int nt = 0; nt < 8; nt++) {
            Ks[(m0 + gid) * AST + nt * 8 + pe]     = tf32r(sacc[nt][0]);
            Ks[(m0 + gid) * AST + nt * 8 + po]     = tf32r(sacc[nt][1]);
            Ks[(m0 + 8 + gid) * AST + nt * 8 + pe] = tf32r(sacc[nt][2]);
            Ks[(m0 + 8 + gid) * AST + nt * 8 + po] = tf32r(sacc[nt][3]);
        }
        __syncwarp();   // warp reads only its own P rows

        // ---- O += P @ V ----
        #pragma unroll
        for (int ks = 0; ks < 8; ks++) {
            int ko = ks * 8 + ko2;
            uint2 lo = *(const uint2*)&Ks[(m0 + gid) * AST + ko];
            uint2 hi = *(const uint2*)&Ks[(m0 + 8 + gid) * AST + ko];
            uint32_t a[4] = { lo.x, hi.x, lo.y, hi.y };
            #pragma unroll
            for (int nt = 0; nt < 8; nt++) {
                uint2 bv = *(const uint2*)&Vs[(nt * 8 + gid) * AST + ko];
                uint32_t b[2] = { bv.x, bv.y };
                mma_tf32(oacc[nt], a, b);
            }
        }
    }

    // ---- finalize: AO rounded + permuted for O-projection GEMM ----
    float inv0 = 1.f / l0, inv1 = 1.f / l1;
    long base = ((long)(bb * T_ + qb * 64 + m0 + gid)) * C_ + h * 64;
    #pragma unroll
    for (int nt = 0; nt < 8; nt++) {
        g_AO[base + nt * 8 + pe]           = tf32r(oacc[nt][0] * inv0);
        g_AO[base + nt * 8 + po]           = tf32r(oacc[nt][1] * inv0);
        g_AO[base + 8L * C_ + nt * 8 + pe] = tf32r(oacc[nt][2] * inv1);
        g_AO[base + 8L * C_ + nt * 8 + po] = tf32r(oacc[nt][3] * inv1);
    }
}

// ---------------------------------------------------------------------------
extern "C" void kernel_launch(void* const* d_in, const int* in_sizes, int n_in,
                              void* d_out, int out_size)
{
    const float* x  = (const float*)d_in[0];
    const float* Wq = (const float*)d_in[1];
    const float* Wk = (const float*)d_in[2];
    const float* Wv = (const float*)d_in[3];
    const float* Wo = (const float*)d_in[4];
    float* out = (float*)d_out;

    float *xr, *Wr, *Q, *K, *V, *Vt, *AO;
    cudaGetSymbolAddress((void**)&xr, g_xr);
    cudaGetSymbolAddress((void**)&Wr, g_Wr);
    cudaGetSymbolAddress((void**)&Q,  g_Q);
    cudaGetSymbolAddress((void**)&K,  g_K);
    cudaGetSymbolAddress((void**)&V,  g_V);
    cudaGetSymbolAddress((void**)&Vt, g_Vt);
    cudaGetSymbolAddress((void**)&AO, g_AO);

    cudaFuncSetAttribute(gemm_tc<0>, cudaFuncAttributeMaxDynamicSharedMemorySize, GEMM_SMEM);
    cudaFuncSetAttribute(gemm_tc<3>, cudaFuncAttributeMaxDynamicSharedMemorySize, GEMM_SMEM);
    cudaFuncSetAttribute(attn_tc,    cudaFuncAttributeMaxDynamicSharedMemorySize, ATTN_SMEM);

    prep_x<<<2048, 256>>>(x, xr);
    prep_w<<<dim3(512, 4), 256>>>(Wq, Wk, Wv, Wo, Wr);

    // Fused QKV projection: B = [Wq; Wk; Wv] rows 0..3071 of g_Wr.
    gemm_tc<3><<<dim3(24, 32), 256, GEMM_SMEM>>>(xr, Wr, nullptr, Q, K, V);

    vtrans<<<dim3(T_ / 32, C_ / 32, B_), dim3(32, 8)>>>();

    attn_tc<<<dim3(T_ / 64, B_ * H_), 128, ATTN_SMEM>>>();

    gemm_tc<0><<<dim3(8, 32), 256, GEMM_SMEM>>>(AO, Wr + 3L * C_ * C_, out,
                                                nullptr, nullptr, nullptr);
}